// round 14
// baseline (speedup 1.0000x reference)
#include <cuda_runtime.h>
#include <cstdint>
#include <cstddef>

#define IND    160   // concat dim
#define EDD    32    // edge feature dim
#define NDD    64    // node feature dim
#define NLAYER 3
#define NMAX   100000
#define TILE   128   // threads per block
#define EPB    128   // edges per block (1 edge per thread)

typedef unsigned long long u64;

// ---- static device scratch (no allocation allowed) ----
__device__ float  d_Wg[NLAYER * IND * EDD];              // g[k] * W1[k][c]
__device__ float  d_S [NLAYER * EDD];                    // col-sums of Wg
__device__ float  d_T [NLAYER * EDD];                    // b·W1 + b1
__device__ float  d_P [(size_t)NMAX * NLAYER * 2 * EDD]; // node-major [n][6][32]
__device__ float2 d_snqn[NMAX];                          // per-node (sum, sumsq)

__device__ __forceinline__ u64 pack2(float lo, float hi) {
    u64 r; asm("mov.b64 %0,{%1,%2};" : "=l"(r) : "f"(lo), "f"(hi)); return r;
}
__device__ __forceinline__ void unpack2(u64 v, float& lo, float& hi) {
    asm("mov.b64 {%0,%1},%2;" : "=f"(lo), "=f"(hi) : "l"(v));
}
__device__ __forceinline__ u64 ffma2(u64 a, u64 b, u64 c) {
    u64 d; asm("fma.rn.f32x2 %0,%1,%2,%3;" : "=l"(d) : "l"(a), "l"(b), "l"(c)); return d;
}
__device__ __forceinline__ u64 add2(u64 a, u64 b) {
    u64 d; asm("add.rn.f32x2 %0,%1,%2;" : "=l"(d) : "l"(a), "l"(b)); return d;
}

// ---------------- prep: fold LayerNorm affine into GEMM1 ----------------
__global__ void prep_kernel(const float* __restrict__ ln_g, const float* __restrict__ ln_b,
                            const float* __restrict__ w1,   const float* __restrict__ b1) {
    __shared__ float wg_sh[IND * 33];
    __shared__ float tb_sh[IND * 33];
    int l = blockIdx.x;
    int tid = threadIdx.x;
    if (tid < IND) {
        int k = tid;
        float gv = ln_g[l * IND + k];
        float bv = ln_b[l * IND + k];
        const float* wrow = w1 + (size_t)(l * IND + k) * EDD;
        #pragma unroll
        for (int c = 0; c < EDD; c++) {
            float wv = wrow[c];
            float wg = gv * wv;
            d_Wg[(size_t)(l * IND + k) * EDD + c] = wg;
            wg_sh[k * 33 + c] = wg;
            tb_sh[k * 33 + c] = bv * wv;
        }
    }
    __syncthreads();
    if (tid < EDD) {
        float s = 0.f, t = 0.f;
        #pragma unroll 8
        for (int k = 0; k < IND; k++) {
            s += wg_sh[k * 33 + tid];
            t += tb_sh[k * 33 + tid];
        }
        d_S[l * EDD + tid] = s;
        d_T[l * EDD + tid] = t + b1[l * EDD + tid];
    }
}

// ---------------- per-node precompute: P[n][ls][c], ls = 2*l + side ----------------
__global__ void __launch_bounds__(TILE)
node_kernel(const float* __restrict__ nf, int N) {
    __shared__ float W_s[NLAYER * 2 * NDD * EDD];   // 48 KB
    const int tid = threadIdx.x;

    const int n = blockIdx.x * TILE + tid;
    const bool v = (n < N);
    const int c = v ? n : 0;

    float x[NDD];
    {
        const float4* r = (const float4*)(nf + (size_t)c * NDD);
        #pragma unroll
        for (int t = 0; t < 16; t++) {
            float4 a = r[t];
            x[4*t] = a.x; x[4*t+1] = a.y; x[4*t+2] = a.z; x[4*t+3] = a.w;
        }
    }
    {
        float s = 0.f, q = 0.f;
        #pragma unroll
        for (int k = 0; k < NDD; k++) { s += x[k]; q = fmaf(x[k], x[k], q); }
        if (v) d_snqn[n] = make_float2(s, q);
    }

    for (int t = tid; t < NLAYER * 2 * NDD * EDD; t += TILE) {
        int ls = t >> 11;
        int r  = t & 2047;
        int l = ls >> 1, side = ls & 1;
        W_s[t] = d_Wg[(size_t)(l * IND + side * NDD) * EDD + r];
    }
    __syncthreads();

    #pragma unroll
    for (int ls = 0; ls < NLAYER * 2; ls++) {
        const float* W = W_s + ls * (NDD * EDD);
        u64 dot[16];
        #pragma unroll
        for (int t = 0; t < 16; t++) dot[t] = 0ull;
        #pragma unroll
        for (int k = 0; k < NDD; k++) {
            u64 xx = pack2(x[k], x[k]);
            const ulonglong2* wr = (const ulonglong2*)(W + k * EDD);
            #pragma unroll
            for (int t = 0; t < 8; t++) {
                ulonglong2 wv = wr[t];
                dot[2*t]   = ffma2(xx, wv.x, dot[2*t]);
                dot[2*t+1] = ffma2(xx, wv.y, dot[2*t+1]);
            }
        }
        if (v) {
            ulonglong2* po = (ulonglong2*)(d_P + ((size_t)n * (NLAYER * 2) + ls) * EDD);
            #pragma unroll
            for (int t = 0; t < 8; t++) {
                ulonglong2 w; w.x = dot[2*t]; w.y = dot[2*t+1];
                po[t] = w;
            }
        }
    }
}

// ---------------- edge kernel: 1 edge per thread ----------------
__global__ void __launch_bounds__(TILE)
edge_kernel(const float* __restrict__ ew_g,
            const float* __restrict__ w2g, const float* __restrict__ b2g,
            const int* __restrict__ ei, const int* __restrict__ ej,
            float* __restrict__ out, int E)
{
    __shared__ float wgE_s[NLAYER * EDD * EDD];   // Wg rows 128..159, per layer
    __shared__ float w2_s [NLAYER * EDD * EDD];
    __shared__ float S_s[NLAYER * EDD], T_s[NLAYER * EDD], b2_s[NLAYER * EDD];

    const int tid = threadIdx.x;
    const long long g0 = (long long)blockIdx.x * EPB + tid;
    const bool v0 = (g0 < E);
    const long long c0 = v0 ? g0 : 0;

    const int i0 = ei[c0], j0 = ej[c0];

    const float2 sqa = d_snqn[i0], sqb = d_snqn[j0];
    const float sb0 = sqa.x + sqb.x, qb0 = sqa.y + sqb.y;

    // edge features -> registers (persist across layers)
    float eA[EDD];
    {
        const float4* r0 = (const float4*)(ew_g + c0 * EDD);
        #pragma unroll
        for (int t = 0; t < 8; t++) {
            float4 a = r0[t];
            eA[4*t] = a.x; eA[4*t+1] = a.y; eA[4*t+2] = a.z; eA[4*t+3] = a.w;
        }
    }

    // layer-0 node-partial sums: 8 LDG.128 per row
    u64 sumA[16];
    {
        const ulonglong2* a0 = (const ulonglong2*)(d_P + ((size_t)i0 * 6 + 0) * EDD);
        const ulonglong2* b0 = (const ulonglong2*)(d_P + ((size_t)j0 * 6 + 1) * EDD);
        #pragma unroll
        for (int t = 0; t < 8; t++) {
            ulonglong2 va = a0[t], vb = b0[t];
            sumA[2*t]   = add2(va.x, vb.x);
            sumA[2*t+1] = add2(va.y, vb.y);
        }
    }

    // stage ALL layers' weights once; only barrier in the kernel
    for (int t = tid; t < NLAYER * EDD * EDD; t += TILE) {
        int l = t >> 10, r = t & 1023;
        wgE_s[t] = d_Wg[(size_t)(l * IND + (IND - EDD)) * EDD + r];
        w2_s[t]  = w2g[t];
    }
    if (tid < NLAYER * EDD) {
        S_s[tid]  = d_S[tid];
        T_s[tid]  = d_T[tid];
        b2_s[tid] = b2g[tid];
    }
    __syncthreads();

    for (int l = 0; l < NLAYER; l++) {
        // ---- GEMM1 edge part (k = 128..159), accumulate from zero ----
        u64 dA[16];
        #pragma unroll
        for (int t = 0; t < 16; t++) dA[t] = 0ull;
        float s0 = sb0, q0 = qb0;

        const float* wl = wgE_s + l * (EDD * EDD);
        #pragma unroll
        for (int k = 0; k < EDD; k++) {
            float xa = eA[k];
            s0 += xa; q0 = fmaf(xa, xa, q0);
            u64 XA = pack2(xa, xa);
            const ulonglong2* wr = (const ulonglong2*)(wl + k * EDD);
            #pragma unroll
            for (int t = 0; t < 8; t++) {
                ulonglong2 wv = wr[t];
                dA[2*t]   = ffma2(XA, wv.x, dA[2*t]);
                dA[2*t+1] = ffma2(XA, wv.y, dA[2*t+1]);
            }
        }

        // fold in node partials (loads completed during the GEMM)
        #pragma unroll
        for (int t = 0; t < 16; t++) dA[t] = add2(dA[t], sumA[t]);

        // prefetch next layer's node partials; latency hides under the epilogue
        if (l + 1 < NLAYER) {
            const ulonglong2* a0 = (const ulonglong2*)(d_P + ((size_t)i0 * 6 + 2*(l+1))     * EDD);
            const ulonglong2* b0 = (const ulonglong2*)(d_P + ((size_t)j0 * 6 + 2*(l+1) + 1) * EDD);
            #pragma unroll
            for (int t = 0; t < 8; t++) {
                ulonglong2 va = a0[t], vb = b0[t];
                sumA[2*t]   = add2(va.x, vb.x);
                sumA[2*t+1] = add2(va.y, vb.y);
            }
        }

        const float* Sl = S_s + l * EDD;
        const float* Tl = T_s + l * EDD;
        const float* w2l = w2_s + l * (EDD * EDD);
        const ulonglong2* b2l = (const ulonglong2*)(b2_s + l * EDD);

        // ---- LN epilogue + LeakyReLU + GEMM2 + residual ----
        float mu  = s0 * (1.f / IND);
        float var = q0 * (1.f / IND) - mu * mu;
        float rs  = rsqrtf(var + 1e-5f);
        float y1[EDD];
        #pragma unroll
        for (int t = 0; t < 16; t++) {
            float a, b; unpack2(dA[t], a, b);
            float u0 = fmaf(rs, a - mu * Sl[2*t],   Tl[2*t]);
            float u1 = fmaf(rs, b - mu * Sl[2*t+1], Tl[2*t+1]);
            y1[2*t]   = fmaxf(u0, 0.01f * u0);
            y1[2*t+1] = fmaxf(u1, 0.01f * u1);
        }
        u64 acc[16];
        #pragma unroll
        for (int t = 0; t < 8; t++) { ulonglong2 v = b2l[t]; acc[2*t] = v.x; acc[2*t+1] = v.y; }
        #pragma unroll
        for (int k = 0; k < EDD; k++) {
            u64 yy = pack2(y1[k], y1[k]);
            const ulonglong2* wr = (const ulonglong2*)(w2l + k * EDD);
            #pragma unroll
            for (int t = 0; t < 8; t++) {
                ulonglong2 wv = wr[t];
                acc[2*t]   = ffma2(yy, wv.x, acc[2*t]);
                acc[2*t+1] = ffma2(yy, wv.y, acc[2*t+1]);
            }
        }
        #pragma unroll
        for (int t = 0; t < 16; t++) {
            float a, b; unpack2(acc[t], a, b);
            eA[2*t] += a; eA[2*t+1] += b;
        }
    }

    if (v0) {
        float4* o = (float4*)(out + g0 * EDD);
        #pragma unroll
        for (int t = 0; t < 8; t++)
            o[t] = make_float4(eA[4*t], eA[4*t+1], eA[4*t+2], eA[4*t+3]);
    }
}

extern "C" void kernel_launch(void* const* d_in, const int* in_sizes, int n_in,
                              void* d_out, int out_size) {
    const float* node_feat = (const float*)d_in[0];
    const float* edge_w    = (const float*)d_in[1];
    const float* ln_g      = (const float*)d_in[2];
    const float* ln_b      = (const float*)d_in[3];
    const float* w1        = (const float*)d_in[4];
    const float* b1        = (const float*)d_in[5];
    const float* w2        = (const float*)d_in[6];
    const float* b2        = (const float*)d_in[7];
    const int*   edge_i    = (const int*)d_in[8];
    const int*   edge_j    = (const int*)d_in[9];
    float* out = (float*)d_out;

    int E = in_sizes[8];
    int N = in_sizes[0] / NDD;
    if (N > NMAX) N = NMAX;

    prep_kernel<<<NLAYER, 192>>>(ln_g, ln_b, w1, b1);
    node_kernel<<<(N + TILE - 1) / TILE, TILE>>>(node_feat, N);

    int grid = (int)((E + EPB - 1) / EPB);
    edge_kernel<<<grid, TILE>>>(edge_w, w2, b2, edge_i, edge_j, out, E);
}

// round 16
// speedup vs baseline: 1.5365x; 1.5365x over previous
#include <cuda_runtime.h>
#include <cuda_fp16.h>
#include <cstdint>
#include <cstddef>

#define IND    160   // concat dim
#define EDD    32    // edge feature dim
#define NDD    64    // node feature dim
#define NLAYER 3
#define NMAX   100000
#define TILE   128   // threads per block
#define EPB    256   // edges per block (2 edges per thread)

typedef unsigned long long u64;

// ---- static device scratch (no allocation allowed) ----
__device__ float  d_Wg[NLAYER * IND * EDD];              // g[k] * W1[k][c]
__device__ float  d_S [NLAYER * EDD];                    // col-sums of Wg
__device__ float  d_T [NLAYER * EDD];                    // b·W1 + b1
__device__ __half d_P [(size_t)NMAX * NLAYER * 2 * EDD]; // node-major [n][6][32], fp16
__device__ float2 d_snqn[NMAX];                          // per-node (sum, sumsq)

__device__ __forceinline__ u64 pack2(float lo, float hi) {
    u64 r; asm("mov.b64 %0,{%1,%2};" : "=l"(r) : "f"(lo), "f"(hi)); return r;
}
__device__ __forceinline__ void unpack2(u64 v, float& lo, float& hi) {
    asm("mov.b64 {%0,%1},%2;" : "=f"(lo), "=f"(hi) : "l"(v));
}
__device__ __forceinline__ u64 ffma2(u64 a, u64 b, u64 c) {
    u64 d; asm("fma.rn.f32x2 %0,%1,%2,%3;" : "=l"(d) : "l"(a), "l"(b), "l"(c)); return d;
}
__device__ __forceinline__ u64 add2(u64 a, u64 b) {
    u64 d; asm("add.rn.f32x2 %0,%1,%2;" : "=l"(d) : "l"(a), "l"(b)); return d;
}

// ---------------- prep: fold LayerNorm affine into GEMM1 ----------------
__global__ void prep_kernel(const float* __restrict__ ln_g, const float* __restrict__ ln_b,
                            const float* __restrict__ w1,   const float* __restrict__ b1) {
    __shared__ float wg_sh[IND * 33];
    __shared__ float tb_sh[IND * 33];
    int l = blockIdx.x;
    int tid = threadIdx.x;
    if (tid < IND) {
        int k = tid;
        float gv = ln_g[l * IND + k];
        float bv = ln_b[l * IND + k];
        const float* wrow = w1 + (size_t)(l * IND + k) * EDD;
        #pragma unroll
        for (int c = 0; c < EDD; c++) {
            float wv = wrow[c];
            float wg = gv * wv;
            d_Wg[(size_t)(l * IND + k) * EDD + c] = wg;
            wg_sh[k * 33 + c] = wg;
            tb_sh[k * 33 + c] = bv * wv;
        }
    }
    __syncthreads();
    if (tid < EDD) {
        float s = 0.f, t = 0.f;
        #pragma unroll 8
        for (int k = 0; k < IND; k++) {
            s += wg_sh[k * 33 + tid];
            t += tb_sh[k * 33 + tid];
        }
        d_S[l * EDD + tid] = s;
        d_T[l * EDD + tid] = t + b1[l * EDD + tid];
    }
}

// ---------------- per-node precompute: P[n][ls][c] (fp16), ls = 2*l + side ----------------
__global__ void __launch_bounds__(TILE)
node_kernel(const float* __restrict__ nf, int N) {
    __shared__ float W_s[NLAYER * 2 * NDD * EDD];   // 48 KB
    const int tid = threadIdx.x;

    const int n = blockIdx.x * TILE + tid;
    const bool v = (n < N);
    const int c = v ? n : 0;

    float x[NDD];
    {
        const float4* r = (const float4*)(nf + (size_t)c * NDD);
        #pragma unroll
        for (int t = 0; t < 16; t++) {
            float4 a = r[t];
            x[4*t] = a.x; x[4*t+1] = a.y; x[4*t+2] = a.z; x[4*t+3] = a.w;
        }
    }
    {
        float s = 0.f, q = 0.f;
        #pragma unroll
        for (int k = 0; k < NDD; k++) { s += x[k]; q = fmaf(x[k], x[k], q); }
        if (v) d_snqn[n] = make_float2(s, q);
    }

    for (int t = tid; t < NLAYER * 2 * NDD * EDD; t += TILE) {
        int ls = t >> 11;
        int r  = t & 2047;
        int l = ls >> 1, side = ls & 1;
        W_s[t] = d_Wg[(size_t)(l * IND + side * NDD) * EDD + r];
    }
    __syncthreads();

    #pragma unroll
    for (int ls = 0; ls < NLAYER * 2; ls++) {
        const float* W = W_s + ls * (NDD * EDD);
        u64 dot[16];
        #pragma unroll
        for (int t = 0; t < 16; t++) dot[t] = 0ull;
        #pragma unroll
        for (int k = 0; k < NDD; k++) {
            u64 xx = pack2(x[k], x[k]);
            const ulonglong2* wr = (const ulonglong2*)(W + k * EDD);
            #pragma unroll
            for (int t = 0; t < 8; t++) {
                ulonglong2 wv = wr[t];
                dot[2*t]   = ffma2(xx, wv.x, dot[2*t]);
                dot[2*t+1] = ffma2(xx, wv.y, dot[2*t+1]);
            }
        }
        if (v) {
            __half2 h[16];
            #pragma unroll
            for (int t = 0; t < 16; t++) {
                float a, b; unpack2(dot[t], a, b);
                h[t] = __floats2half2_rn(a, b);
            }
            uint4* po = (uint4*)(d_P + ((size_t)n * (NLAYER * 2) + ls) * EDD);
            const uint4* hs = (const uint4*)h;
            #pragma unroll
            for (int t = 0; t < 4; t++) po[t] = hs[t];
        }
    }
}

// load a 64B fp16 P row-pair (i-side row + j-side row), sum in fp32 into s[16] (f32x2 packs)
__device__ __forceinline__ void load_pair(u64* s, int i, int j, int ls0) {
    const uint4* a = (const uint4*)(d_P + ((size_t)i * 6 + ls0)     * EDD);
    const uint4* b = (const uint4*)(d_P + ((size_t)j * 6 + ls0 + 1) * EDD);
    uint4 va[4], vb[4];
    #pragma unroll
    for (int t = 0; t < 4; t++) { va[t] = a[t]; vb[t] = b[t]; }
    const __half2* ha = (const __half2*)va;
    const __half2* hb = (const __half2*)vb;
    #pragma unroll
    for (int t = 0; t < 16; t++) {
        float2 fa = __half22float2(ha[t]);
        float2 fb = __half22float2(hb[t]);
        s[t] = pack2(fa.x + fb.x, fa.y + fb.y);
    }
}

// ---------------- edge kernel: 2 edges per thread ----------------
__global__ void __launch_bounds__(TILE)
edge_kernel(const float* __restrict__ ew_g,
            const float* __restrict__ w2g, const float* __restrict__ b2g,
            const int* __restrict__ ei, const int* __restrict__ ej,
            float* __restrict__ out, int E)
{
    __shared__ float wgE_s[NLAYER * EDD * EDD];   // Wg rows 128..159, per layer
    __shared__ float w2_s [NLAYER * EDD * EDD];
    __shared__ float S_s[NLAYER * EDD], T_s[NLAYER * EDD], b2_s[NLAYER * EDD];

    const int tid = threadIdx.x;
    const long long base = (long long)blockIdx.x * EPB;
    const long long g0 = base + tid, g1 = g0 + TILE;
    const bool v0 = (g0 < E), v1 = (g1 < E);
    const long long c0 = v0 ? g0 : 0, c1 = v1 ? g1 : 0;

    const int i0 = ei[c0], j0 = ej[c0];
    const int i1 = ei[c1], j1 = ej[c1];

    const float2 sqa = d_snqn[i0], sqb = d_snqn[j0];
    const float2 sqc = d_snqn[i1], sqd = d_snqn[j1];
    const float sb0 = sqa.x + sqb.x, qb0 = sqa.y + sqb.y;
    const float sb1 = sqc.x + sqd.x, qb1 = sqc.y + sqd.y;

    // edge features -> registers (persist across layers)
    float eA[EDD], eB[EDD];
    {
        const float4* r0 = (const float4*)(ew_g + c0 * EDD);
        const float4* r1 = (const float4*)(ew_g + c1 * EDD);
        #pragma unroll
        for (int t = 0; t < 8; t++) {
            float4 a = r0[t], b = r1[t];
            eA[4*t] = a.x; eA[4*t+1] = a.y; eA[4*t+2] = a.z; eA[4*t+3] = a.w;
            eB[4*t] = b.x; eB[4*t+1] = b.y; eB[4*t+2] = b.z; eB[4*t+3] = b.w;
        }
    }

    // layer-0 node-partial sums (fp16 rows, fp32 accumulation)
    u64 sumA[16], sumB[16];
    load_pair(sumA, i0, j0, 0);
    load_pair(sumB, i1, j1, 0);

    // stage ALL layers' weights once; only barrier in the kernel
    for (int t = tid; t < NLAYER * EDD * EDD; t += TILE) {
        int l = t >> 10, r = t & 1023;
        wgE_s[t] = d_Wg[(size_t)(l * IND + (IND - EDD)) * EDD + r];
        w2_s[t]  = w2g[t];
    }
    if (tid < NLAYER * EDD) {
        S_s[tid]  = d_S[tid];
        T_s[tid]  = d_T[tid];
        b2_s[tid] = b2g[tid];
    }
    __syncthreads();

    for (int l = 0; l < NLAYER; l++) {
        // ---- GEMM1 edge part (k = 128..159), accumulate from zero ----
        u64 dA[16], dB[16];
        #pragma unroll
        for (int t = 0; t < 16; t++) { dA[t] = 0ull; dB[t] = 0ull; }
        float s0 = sb0, q0 = qb0, s1 = sb1, q1 = qb1;

        const float* wl = wgE_s + l * (EDD * EDD);
        #pragma unroll
        for (int k = 0; k < EDD; k++) {
            float xa = eA[k], xb = eB[k];
            s0 += xa; q0 = fmaf(xa, xa, q0);
            s1 += xb; q1 = fmaf(xb, xb, q1);
            u64 XA = pack2(xa, xa), XB = pack2(xb, xb);
            const ulonglong2* wr = (const ulonglong2*)(wl + k * EDD);
            #pragma unroll
            for (int t = 0; t < 8; t++) {
                ulonglong2 wv = wr[t];
                dA[2*t]   = ffma2(XA, wv.x, dA[2*t]);
                dA[2*t+1] = ffma2(XA, wv.y, dA[2*t+1]);
                dB[2*t]   = ffma2(XB, wv.x, dB[2*t]);
                dB[2*t+1] = ffma2(XB, wv.y, dB[2*t+1]);
            }
        }

        // fold in node partials (loads completed during the GEMM)
        #pragma unroll
        for (int t = 0; t < 16; t++) {
            dA[t] = add2(dA[t], sumA[t]);
            dB[t] = add2(dB[t], sumB[t]);
        }

        // prefetch next layer's node partials; latency hides under epilogues
        if (l + 1 < NLAYER) {
            load_pair(sumA, i0, j0, 2 * (l + 1));
            load_pair(sumB, i1, j1, 2 * (l + 1));
        }

        const float* Sl = S_s + l * EDD;
        const float* Tl = T_s + l * EDD;
        const float* w2l = w2_s + l * (EDD * EDD);
        const ulonglong2* b2l = (const ulonglong2*)(b2_s + l * EDD);

        // ---- edge A: LN epilogue + LeakyReLU + GEMM2 + residual ----
        {
            float mu  = s0 * (1.f / IND);
            float var = q0 * (1.f / IND) - mu * mu;
            float rs  = rsqrtf(var + 1e-5f);
            float y1[EDD];
            #pragma unroll
            for (int t = 0; t < 16; t++) {
                float a, b; unpack2(dA[t], a, b);
                float u0 = fmaf(rs, a - mu * Sl[2*t],   Tl[2*t]);
                float u1 = fmaf(rs, b - mu * Sl[2*t+1], Tl[2*t+1]);
                y1[2*t]   = fmaxf(u0, 0.01f * u0);
                y1[2*t+1] = fmaxf(u1, 0.01f * u1);
            }
            u64 acc[16];
            #pragma unroll
            for (int t = 0; t < 8; t++) { ulonglong2 v = b2l[t]; acc[2*t] = v.x; acc[2*t+1] = v.y; }
            #pragma unroll
            for (int k = 0; k < EDD; k++) {
                u64 yy = pack2(y1[k], y1[k]);
                const ulonglong2* wr = (const ulonglong2*)(w2l + k * EDD);
                #pragma unroll
                for (int t = 0; t < 8; t++) {
                    ulonglong2 wv = wr[t];
                    acc[2*t]   = ffma2(yy, wv.x, acc[2*t]);
                    acc[2*t+1] = ffma2(yy, wv.y, acc[2*t+1]);
                }
            }
            #pragma unroll
            for (int t = 0; t < 16; t++) {
                float a, b; unpack2(acc[t], a, b);
                eA[2*t] += a; eA[2*t+1] += b;
            }
        }
        // ---- edge B ----
        {
            float mu  = s1 * (1.f / IND);
            float var = q1 * (1.f / IND) - mu * mu;
            float rs  = rsqrtf(var + 1e-5f);
            float y1[EDD];
            #pragma unroll
            for (int t = 0; t < 16; t++) {
                float a, b; unpack2(dB[t], a, b);
                float u0 = fmaf(rs, a - mu * Sl[2*t],   Tl[2*t]);
                float u1 = fmaf(rs, b - mu * Sl[2*t+1], Tl[2*t+1]);
                y1[2*t]   = fmaxf(u0, 0.01f * u0);
                y1[2*t+1] = fmaxf(u1, 0.01f * u1);
            }
            u64 acc[16];
            #pragma unroll
            for (int t = 0; t < 8; t++) { ulonglong2 v = b2l[t]; acc[2*t] = v.x; acc[2*t+1] = v.y; }
            #pragma unroll
            for (int k = 0; k < EDD; k++) {
                u64 yy = pack2(y1[k], y1[k]);
                const ulonglong2* wr = (const ulonglong2*)(w2l + k * EDD);
                #pragma unroll
                for (int t = 0; t < 8; t++) {
                    ulonglong2 wv = wr[t];
                    acc[2*t]   = ffma2(yy, wv.x, acc[2*t]);
                    acc[2*t+1] = ffma2(yy, wv.y, acc[2*t+1]);
                }
            }
            #pragma unroll
            for (int t = 0; t < 16; t++) {
                float a, b; unpack2(acc[t], a, b);
                eB[2*t] += a; eB[2*t+1] += b;
            }
        }
    }

    if (v0) {
        float4* o = (float4*)(out + g0 * EDD);
        #pragma unroll
        for (int t = 0; t < 8; t++)
            o[t] = make_float4(eA[4*t], eA[4*t+1], eA[4*t+2], eA[4*t+3]);
    }
    if (v1) {
        float4* o = (float4*)(out + g1 * EDD);
        #pragma unroll
        for (int t = 0; t < 8; t++)
            o[t] = make_float4(eB[4*t], eB[4*t+1], eB[4*t+2], eB[4*t+3]);
    }
}

extern "C" void kernel_launch(void* const* d_in, const int* in_sizes, int n_in,
                              void* d_out, int out_size) {
    const float* node_feat = (const float*)d_in[0];
    const float* edge_w    = (const float*)d_in[1];
    const float* ln_g      = (const float*)d_in[2];
    const float* ln_b      = (const float*)d_in[3];
    const float* w1        = (const float*)d_in[4];
    const float* b1        = (const float*)d_in[5];
    const float* w2        = (const float*)d_in[6];
    const float* b2        = (const float*)d_in[7];
    const int*   edge_i    = (const int*)d_in[8];
    const int*   edge_j    = (const int*)d_in[9];
    float* out = (float*)d_out;

    int E = in_sizes[8];
    int N = in_sizes[0] / NDD;
    if (N > NMAX) N = NMAX;

    prep_kernel<<<NLAYER, 192>>>(ln_g, ln_b, w1, b1);
    node_kernel<<<(N + TILE - 1) / TILE, TILE>>>(node_feat, N);

    int grid = (int)((E + EPB - 1) / EPB);
    edge_kernel<<<grid, TILE>>>(edge_w, w2, b2, edge_i, edge_j, out, E);
}